// round 17
// baseline (speedup 1.0000x reference)
#include <cuda_runtime.h>
#include <cuda_fp16.h>
#include <cstdint>

// Problem constants
#define NB     64
#define OC     128
#define BATCH  4
#define TLEN   1024
#define FBINS  1025
#define TM     128     // t rows per CTA
#define KC     64      // K per smem buffer (4 x m16n8k16 steps)
#define FBMAX  897     // FBINS - 128: max window base
#define KKPAD  256     // 2 channels x 128 window bins

// Smem: 2 tiles per buffer (A, B), 128 rows x 144B (128B data + 16B pad).
// RSTR=144: 16B-aligned rows; 9x16B per row, gcd(9,8)=1 -> ldmatrix/STS.128
// conflict-free across 8-row phases.
#define RSTR   144
#define BUFSZ  36864            // 2 tiles x 128 x 144
#define T_A    0
#define T_B    18432
#define SM_BIAS 73728           // float[128]
#define SM_BYTES 74240

// Device scratch
__device__ float    g_scr[NB * BATCH * TLEN * OC];  // (k,b,t,o)
__device__ unsigned g_b16[NB * OC * (KKPAD / 2)];   // B' fp16 [k][o][kkpad]
__device__ int      g_fb[NB];                        // per-band window base

typedef unsigned u32;

__device__ __forceinline__ u32 smem_u32(const void* p) {
    u32 a;
    asm("{ .reg .u64 t; cvta.to.shared.u64 t, %1; cvt.u32.u64 %0, t; }" : "=r"(a) : "l"(p));
    return a;
}
__device__ __forceinline__ void cp16(u32 dst, const void* src) {
    asm volatile("cp.async.cg.shared.global [%0], [%1], 16;" :: "r"(dst), "l"(src) : "memory");
}
__device__ __forceinline__ void cp_commit() { asm volatile("cp.async.commit_group;" ::: "memory"); }
__device__ __forceinline__ void cp_wait0()  { asm volatile("cp.async.wait_group 0;" ::: "memory"); }

#define LDX4(r, addr) \
    asm volatile("ldmatrix.sync.aligned.m8n8.x4.shared.b16 {%0,%1,%2,%3}, [%4];" \
        : "=r"((r)[0]), "=r"((r)[1]), "=r"((r)[2]), "=r"((r)[3]) : "r"(addr))

#define MMA(d, A, b0, b1) \
    asm volatile("mma.sync.aligned.m16n8k16.row.col.f32.f16.f16.f32 " \
        "{%0,%1,%2,%3}, {%4,%5,%6,%7}, {%8,%9}, {%0,%1,%2,%3};" \
        : "+f"((d)[0]), "+f"((d)[1]), "+f"((d)[2]), "+f"((d)[3]) \
        : "r"((A)[0]), "r"((A)[1]), "r"((A)[2]), "r"((A)[3]), "r"(b0), "r"(b1))

// ---------------------------------------------------------------------------
// fb_kern: per-band dense window base fb[k] = min(first support bin, 897).
// ---------------------------------------------------------------------------
__global__ void fb_kern(const int* __restrict__ idx, int W) {
    int k = threadIdx.x;
    int f0 = idx[k * W];
    g_fb[k] = (f0 > FBMAX) ? FBMAX : f0;
}

// ---------------------------------------------------------------------------
// prepB (absolute-f): B'[k][o][c*128+j] = fp16(mel[k][w]*pre_w[k][c][w][o]),
// w = fb[k] + j - f0; zero outside [0, W). 32kk x 32o tiles, grid (8, NB, 4).
// ---------------------------------------------------------------------------
__global__ __launch_bounds__(256) void prepB(const float* __restrict__ pre_w,
                                             const float* __restrict__ mel_w,
                                             const int* __restrict__ idx, int W) {
    __shared__ float tile[32][33];
    int ch = blockIdx.x, k = blockIdx.y, og = blockIdx.z, tid = threadIdx.x;
    int f0 = idx[k * W];
    int fb = g_fb[k];
#pragma unroll
    for (int i = 0; i < 4; i++) {
        int e = tid + i * 256;             // 0..1023
        int kkL = e >> 5, oL = e & 31;
        int kkg = ch * 32 + kkL;           // 0..255
        int c = kkg >> 7, j = kkg & 127;
        int w = fb + j - f0;
        float v = 0.f;
        if (w >= 0 && w < W)
            v = mel_w[k * W + w] * pre_w[((size_t)(k * 2 + c) * W + w) * OC + og * 32 + oL];
        tile[kkL][oL] = v;
    }
    __syncthreads();
    unsigned short* bp = (unsigned short*)g_b16;
#pragma unroll
    for (int i = 0; i < 4; i++) {
        int e = tid + i * 256;
        int oL = e >> 5, kkL = e & 31;
        bp[(size_t)(k * OC + og * 32 + oL) * KKPAD + ch * 32 + kkL] =
            __half_as_ushort(__float2half_rn(tile[kkL][oL]));
    }
}

// ---------------------------------------------------------------------------
// Tensor-core band GEMM, fp16, dense-window A (no gather), KC=64 chunks.
// CTA (k, b, t-tile 128); 8 warps 4x2; warp tile 32x64; 4 chunks, 1 bar/chunk.
// chunk ch covers kk in [64ch, 64ch+64): c = ch>>1, f-half = ch&1.
// K-step stride inside a row: 16 fp16 = 32 BYTES (ks*32 — R16's NaN was ks*64
// reading unwritten smem pad as fp16 NaN).
// ---------------------------------------------------------------------------
__global__ __launch_bounds__(256, 2) void gemm_mma(
    const float* __restrict__ x, const float* __restrict__ bias) {
    extern __shared__ char smem[];
    const u32 sb = smem_u32(smem);
    const int tid = threadIdx.x, wid = tid >> 5, lane = tid & 31;
    const int k = blockIdx.z, b = blockIdx.y, t0 = blockIdx.x * TM;
    const int wm = wid >> 1, wn = wid & 1;
    const int mbase = wm * 32, nbase = wn * 64;

    float* bias_s = (float*)(smem + SM_BIAS);
    if (tid < 128) bias_s[tid] = bias[k * OC + tid];
    const int fb = g_fb[k];
    __syncthreads();

    // --- A: thread owns row (tid>>1), cols jb..jb+31 of the 64-col chunk ---
    const int rowA = tid >> 1;
    const int jb = (tid & 1) * 32;
    float aF[32];
    auto loadA = [&](int ch) {             // pure dense loads, no gather
        int c = ch >> 1, fh = ch & 1;
        const float* p = x + ((size_t)((b * 2 + c) * TLEN + t0 + rowA)) * FBINS
                       + fb + fh * 64 + jb;
#pragma unroll
        for (int q = 0; q < 32; q++) aF[q] = p[q];
    };
    auto stsA = [&](u32 off) {             // cvt + pack + 4x STS.128
        u32 hbuf[16];
#pragma unroll
        for (int s = 0; s < 16; s++) {
            __half2 hv = __floats2half2_rn(aF[2 * s], aF[2 * s + 1]);
            hbuf[s] = *(u32*)&hv;
        }
        u32 ba = off + T_A + (u32)rowA * RSTR + (u32)jb * 2;
#pragma unroll
        for (int s4 = 0; s4 < 4; s4++) {
            uint4 v; v.x = hbuf[4 * s4]; v.y = hbuf[4 * s4 + 1];
            v.z = hbuf[4 * s4 + 2]; v.w = hbuf[4 * s4 + 3];
            *(uint4*)(smem + ba + 16 * s4) = v;
        }
    };
    // --- B: 4x cp.async 16B per thread per chunk (64B per thread) ---
    const int oB = tid >> 1, segB = tid & 1;
    const u32* brow = g_b16 + (size_t)(k * OC + oB) * (KKPAD / 2);
    auto issueB = [&](int ch, u32 off) {
        const u32* src = brow + ch * 32 + segB * 16;
        u32 dst = sb + off + T_B + (u32)oB * RSTR + (u32)segB * 64;
#pragma unroll
        for (int q = 0; q < 4; q++) cp16(dst + 16 * q, src + 4 * q);
        cp_commit();
    };

    float acc[2][8][4];
#pragma unroll
    for (int mt = 0; mt < 2; mt++)
#pragma unroll
        for (int nt = 0; nt < 8; nt++)
#pragma unroll
            for (int j = 0; j < 4; j++) acc[mt][nt][j] = 0.f;

    issueB(0, 0);
    loadA(0);

#pragma unroll 1
    for (int ch = 0; ch < 4; ch++) {
        const u32 off = (u32)(ch & 1) * BUFSZ;
        stsA(off);
        cp_wait0();
        __syncthreads();                   // single barrier per chunk
        if (ch + 1 < 4) { issueB(ch + 1, off ^ BUFSZ); loadA(ch + 1); }

#pragma unroll
        for (int ks = 0; ks < 4; ks++) {
            u32 af[2][4];
#pragma unroll
            for (int mt = 0; mt < 2; mt++) {
                u32 aaddr = sb + off + T_A + (u32)(mbase + mt * 16 + (lane & 15)) * RSTR
                          + (u32)ks * 32 + ((u32)(lane >> 4) << 4);
                LDX4(af[mt], aaddr);
            }
#pragma unroll
            for (int np = 0; np < 4; np++) {
                int rn = nbase + np * 16 + (lane & 7) + ((lane >> 1) & 8);
                u32 baddr = sb + off + T_B + (u32)rn * RSTR + (u32)ks * 32
                          + (((u32)(lane >> 3) & 1) << 4);
                u32 bf[4];
                LDX4(bf, baddr);
#pragma unroll
                for (int h = 0; h < 2; h++) {
                    int nt = np * 2 + h;
#pragma unroll
                    for (int mt = 0; mt < 2; mt++)
                        MMA(acc[mt][nt], af[mt], bf[2 * h], bf[2 * h + 1]);
                }
            }
        }
        // trailing barrier elided: next stsA targets the other buffer, whose
        // readers all passed this chunk's barrier after finishing its compute.
    }

    // Epilogue: bias + store (k,b,t,o)
#pragma unroll
    for (int mt = 0; mt < 2; mt++) {
        int m0 = mbase + mt * 16 + (lane >> 2);
        float* base0 = g_scr + ((size_t)(k * BATCH + b) * TLEN + t0 + m0) * OC;
        float* base1 = base0 + 8 * OC;
#pragma unroll
        for (int nt = 0; nt < 8; nt++) {
            int o0 = nbase + nt * 8 + (lane & 3) * 2;
            float2 bb = *(float2*)(bias_s + o0);
            float2 v0, v1;
            v0.x = acc[mt][nt][0] + bb.x; v0.y = acc[mt][nt][1] + bb.y;
            v1.x = acc[mt][nt][2] + bb.x; v1.y = acc[mt][nt][3] + bb.y;
            *(float2*)(base0 + o0) = v0;
            *(float2*)(base1 + o0) = v1;
        }
    }
}

// ---------------------------------------------------------------------------
// Transpose (k,b,t,o) -> (b,o,t,k)
// ---------------------------------------------------------------------------
__global__ __launch_bounds__(256) void trans_kernel(float* __restrict__ out) {
    __shared__ float sm[NB][OC + 1];
    int t = blockIdx.x, b = blockIdx.y, tid = threadIdx.x;
    const float* src = g_scr + ((size_t)b * TLEN + t) * OC;
#pragma unroll
    for (int i = 0; i < 32; i++) {
        int e = tid + i * 256;
        int kk = e >> 7, o = e & 127;
        sm[kk][o] = src[(size_t)kk * (BATCH * TLEN * OC) + o];
    }
    __syncthreads();
    float* dst = out + ((size_t)b * OC) * (TLEN * (size_t)NB) + (size_t)t * NB;
#pragma unroll
    for (int i = 0; i < 32; i++) {
        int e = tid + i * 256;
        int o = e >> 6, kk = e & 63;
        dst[(size_t)o * (TLEN * NB) + kk] = sm[kk][o];
    }
}

// ---------------------------------------------------------------------------
extern "C" void kernel_launch(void* const* d_in, const int* in_sizes, int n_in,
                              void* d_out, int out_size) {
    const float* x     = (const float*)d_in[0];
    const int*   idx   = (const int*)  d_in[1];
    const float* mel_w = (const float*)d_in[2];
    const float* pre_w = (const float*)d_in[3];
    const float* pre_b = (const float*)d_in[4];
    float* out = (float*)d_out;

    int W = in_sizes[1] / NB;

    cudaFuncSetAttribute(gemm_mma, cudaFuncAttributeMaxDynamicSharedMemorySize, SM_BYTES);

    fb_kern<<<1, NB>>>(idx, W);
    prepB<<<dim3(KKPAD / 32, NB, 4), 256>>>(pre_w, mel_w, idx, W);
    gemm_mma<<<dim3(TLEN / TM, BATCH, NB), 256, SM_BYTES>>>(x, pre_b);
    trans_kernel<<<dim3(TLEN, BATCH), 256>>>(out);
}